// round 12
// baseline (speedup 1.0000x reference)
#include <cuda_runtime.h>
#include <math.h>

#define BB 4
#define LL 2048
#define DD 64
#define NGRP 16          // groups per batch
#define NCH 16           // 8-event chunks per group
#define GEVT 128         // events per group

typedef unsigned long long u64_t;

// Scratch (no cudaMalloc allowed). Flags are monotonic across launches; g_acc64 is
// reset to 0 by the tail block at the end of every launch (launches serialize).
__device__ float g_gcsum[BB][NGRP][DD];
__device__ float g_gesum[BB][NGRP][DD];
__device__ float g_gvsum[BB][NGRP][DD];
__device__ float g_gusum[BB][NGRP];
__device__ int   g_flag[BB][NGRP];   // +1 per launch (launch-relative generations)
__device__ u64_t g_acc64[BB];        // (fixedpoint_sum << 8) | block_count

__device__ __forceinline__ float warp_sum(float v) {
#pragma unroll
    for (int o = 16; o > 0; o >>= 1) v += __shfl_xor_sync(0xffffffffu, v, o);
    return v;
}

// ---- packed f32x2 helpers (FFMA2 path, PTX-only) ----
__device__ __forceinline__ u64_t mul2(u64_t a, u64_t b) {
    u64_t d; asm("mul.rn.f32x2 %0, %1, %2;" : "=l"(d) : "l"(a), "l"(b)); return d;
}
__device__ __forceinline__ u64_t fma2(u64_t a, u64_t b, u64_t c) {
    u64_t d; asm("fma.rn.f32x2 %0, %1, %2, %3;" : "=l"(d) : "l"(a), "l"(b), "l"(c)); return d;
}
__device__ __forceinline__ u64_t add2(u64_t a, u64_t b) {
    u64_t d; asm("add.rn.f32x2 %0, %1, %2;" : "=l"(d) : "l"(a), "l"(b)); return d;
}
__device__ __forceinline__ u64_t pk2(float x, float y) {
    u64_t d; asm("mov.b64 %0, {%1, %2};" : "=l"(d) : "f"(x), "f"(y)); return d;
}
__device__ __forceinline__ float2 up2(u64_t v) {
    float2 r; asm("mov.b64 {%0, %1}, %2;" : "=f"(r.x), "=f"(r.y) : "l"(v)); return r;
}

__device__ __forceinline__ int ld_acq(const int* p) {
    int v;
    asm volatile("ld.acquire.gpu.u32 %0, [%1];" : "=r"(v) : "l"(p) : "memory");
    return v;
}
__device__ __forceinline__ void st_rel(int* p, int v) {
    asm volatile("st.release.gpu.u32 [%0], %1;" :: "l"(p), "r"(v) : "memory");
}
__device__ __forceinline__ u64_t atom_add_acqrel(u64_t* p, u64_t v) {
    u64_t r;
    asm volatile("atom.acq_rel.gpu.add.u64 %0, [%1], %2;"
                 : "=l"(r) : "l"(p), "l"(v) : "memory");
    return r;
}

__global__ __launch_bounds__(512) void hawkes_fused(
    const int* __restrict__ ids, const float* __restrict__ times,
    const float* __restrict__ emb, const float* __restrict__ u_table,
    const float* __restrict__ beta, float* __restrict__ out)
{
    const int bg   = blockIdx.x;
    const int b    = bg >> 4;          // batch
    const int cg   = bg & 15;          // group
    const int tid  = threadIdx.x;
    const int lane = tid & 31;
    const int warp = tid >> 5;         // 0..15
    const int r    = tid >> 6;         // gather row-slice, 0..7 (16 events each)
    const int d    = tid & 63;

    __shared__ __align__(16) float sE[GEVT][68];   // E rows, padded (272B row)
    __shared__ float sw[GEVT], sme[GEVT], svw[GEVT];
    __shared__ __align__(16) float sCs[NCH][DD];   // per-8-chunk csum
    __shared__ float sEs[NCH][DD], sVs[NCH][DD];   // (tail reuses as scratch)
    __shared__ __align__(16) float spb[NCH][DD];   // per-8-chunk exclusive prefix
    __shared__ float sP[16][32];                   // phase-C d-slice partials
    __shared__ float sures[4], slog[4], sbase[2];
    __shared__ int   stail;
    __shared__ u64_t sfin;

    const float ab  = fabsf(beta[0]);
    const int   gen = g_flag[b][cg] + 1;   // own flag's pre-launch value (broadcast load)

    // ---- direct id loads (broadcast LDGs) — emb gather issues before any barrier ----
    const int cbase = b * LL + cg * GEVT + r * 16;
    int idv[16];
#pragma unroll
    for (int jj = 0; jj < 16; ++jj) idv[jj] = ids[cbase + jj];

    // ---- init warps (0,4,8,12 -> own 32-event quartet): per-event scalars; u in register ----
    float u_reg = 0.f;
    if ((warp & 3) == 0) {
        const int qe   = warp >> 2;
        const int gidx = b * LL + cg * GEVT + qe * 32 + lane;
        int id = ids[gidx];
        float tj    = times[gidx] * 1e-4f;
        float tlast = times[b * LL + LL - 1] * 1e-4f;
        float w = __expf(ab * tj);
        sw [qe * 32 + lane] = w;
        sme[qe * 32 + lane] = __expf(-ab * tj);
        svw[qe * 32 + lane] = 1.0f - __expf(-ab * tlast) * w;
        u_reg = u_table[id];
    }

    // ---- emb gather (independent LDGs in flight across the barrier) ----
    float ev[16];
#pragma unroll
    for (int jj = 0; jj < 16; ++jj) ev[jj] = emb[(long)idv[jj] * DD + d];
    __syncthreads();   // B1: sw/sme/svw ready

    // ---- consume: store sE rows + per-8-chunk sums (chunks 2r and 2r+1) ----
    float cs0 = 0.f, es0 = 0.f, vs0 = 0.f, cs1 = 0.f, es1 = 0.f, vs1 = 0.f;
#pragma unroll
    for (int jj = 0; jj < 8; ++jj) {
        int j = r * 16 + jj;
        float e = ev[jj];
        sE[j][d] = e;
        cs0 = fmaf(e, sw[j], cs0); es0 += e; vs0 = fmaf(e, svw[j], vs0);
    }
#pragma unroll
    for (int jj = 8; jj < 16; ++jj) {
        int j = r * 16 + jj;
        float e = ev[jj];
        sE[j][d] = e;
        cs1 = fmaf(e, sw[j], cs1); es1 += e; vs1 = fmaf(e, svw[j], vs1);
    }
    sCs[2 * r][d] = cs0;  sCs[2 * r + 1][d] = cs1;
    sEs[2 * r][d] = es0;  sEs[2 * r + 1][d] = es1;
    sVs[2 * r][d] = vs0;  sVs[2 * r + 1][d] = vs1;
    if ((warp & 3) == 0) {
        float uv = warp_sum(fabsf(u_reg));
        if (lane == 0) sures[warp >> 2] = uv;
    }
    __syncthreads();   // B2: sE/sCs/sEs/sVs ready

    // ---- warp-specialized publish on HIGH-priority warps (hi-wid-first arbiter):
    //      warp 15 = csum+flag (never starved by Gram warps on its SMSP),
    //      warp 14 = poll, warps 12/13 = tail-only sums.
    if (warp == 15) {                   // csum total -> global, then flag release
        float2 t = make_float2(0.f, 0.f);
#pragma unroll
        for (int k = 0; k < NCH; ++k) {
            float2 v = *reinterpret_cast<const float2*>(&sCs[k][lane * 2]);
            t.x += v.x; t.y += v.y;
        }
        *reinterpret_cast<float2*>(&g_gcsum[b][cg][lane * 2]) = t;
        __syncwarp();
        if (lane == 0) st_rel(&g_flag[b][cg], gen);
    } else if (warp == 14) {            // poll earlier groups
        if (lane < cg) {
            const int* fp = &g_flag[b][lane];
            while (ld_acq(fp) < gen) { }
        }
    } else if (warp == 12 || warp == 13) {  // tail-only sums
        const int dd = (warp - 12) * 32 + lane;
        float te = 0.f, tv = 0.f;
#pragma unroll
        for (int k = 0; k < NCH; ++k) { te += sEs[k][dd]; tv += sVs[k][dd]; }
        g_gesum[b][cg][dd] = te;
        g_gvsum[b][cg][dd] = tv;
        if (dd == 0) g_gusum[b][cg] = sures[0] + sures[1] + sures[2] + sures[3];
    }

    // ---- Gram (packed f32x2): warp = (quartet p, D-slice qC); 4×8-lane subgroups,
    //      lanes (hsel..hsel+7) <-> chunk p*4 + hsel/8. 8 j-iters.
    const int p = warp >> 2, qC = warp & 3;
    const int hsel = lane & 24;            // 0,8,16,24: chunk-of-8 within the quartet
    const int isub = lane & 7;             // event index within the 8-chunk
    const ulonglong2* arow =
        reinterpret_cast<const ulonglong2*>(&sE[p * 32 + lane][qC * 16]);
    ulonglong2 A0 = arow[0], A1 = arow[1], A2 = arow[2], A3 = arow[3];
    u64_t part2 = 0ULL;
#pragma unroll
    for (int j = 0; j < 8; ++j) {
        const ulonglong2* ej =
            reinterpret_cast<const ulonglong2*>(&sE[p * 32 + hsel + j][qC * 16]);
        ulonglong2 B0 = ej[0], B1 = ej[1], B2 = ej[2], B3 = ej[3];
        u64_t s = mul2(A0.x, B0.x);
        s = fma2(A0.y, B0.y, s);
        s = fma2(A1.x, B1.x, s);
        s = fma2(A1.y, B1.y, s);
        s = fma2(A2.x, B2.x, s);
        s = fma2(A2.y, B2.y, s);
        s = fma2(A3.x, B3.x, s);
        s = fma2(A3.y, B3.y, s);
        float m = (j < isub) ? sw[p * 32 + hsel + j] : 0.f;   // strict lower triangle
        part2 = fma2(pk2(m, m), s, part2);
    }
    __syncthreads();   // B3: polls + publishes complete (release visibility block-wide)

    // ---- exclusive prefix directly in the spb threads (coalesced, MLP-15) ----
    if (tid < DD) {
        float run = 0.f;
#pragma unroll
        for (int cp = 0; cp < NGRP - 1; ++cp) {
            float v = (cp < cg) ? __ldcg(&g_gcsum[b][cp][tid]) : 0.f;
            run += v;
        }
        spb[0][tid] = run;
#pragma unroll
        for (int k = 0; k < NCH - 1; ++k) {
            run += sCs[k][tid];
            spb[k + 1][tid] = run;
        }
    }
    __syncthreads();   // B4: spb ready

    // ---- add e_i·P term (per-8-chunk prefix) and fold to scalar ----
    {
        const int cidx = p * 4 + (lane >> 3);
        const ulonglong2* pb = reinterpret_cast<const ulonglong2*>(&spb[cidx][qC * 16]);
        ulonglong2 P0 = pb[0], P1 = pb[1], P2 = pb[2], P3 = pb[3];
        u64_t s = mul2(A0.x, P0.x);
        s = fma2(A0.y, P0.y, s);
        s = fma2(A1.x, P1.x, s);
        s = fma2(A1.y, P1.y, s);
        s = fma2(A2.x, P2.x, s);
        s = fma2(A2.y, P2.y, s);
        s = fma2(A3.x, P3.x, s);
        s = fma2(A3.y, P3.y, s);
        part2 = add2(part2, s);
        float2 f = up2(part2);
        sP[warp][lane] = f.x + f.y;
    }
    __syncthreads();   // B5
    if ((warp & 3) == 0) {
        const int pp = warp >> 2;      // quartet pp: lanes span its 32 events
        float dp  = sP[pp * 4][lane] + sP[pp * 4 + 1][lane]
                  + sP[pp * 4 + 2][lane] + sP[pp * 4 + 3][lane];
        float s1  = ab * sme[pp * 32 + lane] * dp;
        float lam = fabsf(s1 + fabsf(u_reg)) + 1e-6f;
        float v   = warp_sum(-__logf(lam));
        if (lane == 0) slog[pp] = v;
    }
    __syncthreads();   // B6

    // ---- single packed atomic: fixed-point sum (deterministic) + block count ----
    if (tid == 0) {
        float tot = slog[0] + slog[1] + slog[2] + slog[3];
        long long fx = llrintf(tot * 1048576.0f);          // 2^20 fixed point
        u64_t pkv = ((u64_t)fx << 8) | 1ULL;
        u64_t ret = atom_add_acqrel(&g_acc64[b], pkv);
        stail = ((ret & 0xFFULL) == (u64_t)(NGRP - 1)) ? 1 : 0;
        sfin  = ret + pkv;
    }
    __syncthreads();   // B7

    // ---- tail block: base (integral) term + final output + accumulator reset ----
    if (stail) {
        __threadfence();
        const int i16 = tid >> 4;
        const int d4  = (tid & 15) * 4;
        if (tid < 256) {   // Et/Vt rows into smem scratch (sEs/sVs reusable now)
            *reinterpret_cast<float4*>(&sEs[i16][d4]) =
                *reinterpret_cast<const float4*>(&g_gesum[b][i16][d4]);
            *reinterpret_cast<float4*>(&sVs[i16][d4]) =
                *reinterpret_cast<const float4*>(&g_gvsum[b][i16][d4]);
        }
        if (tid < NGRP) spb[0][tid] = __ldcg(&g_gusum[b][tid]);
        __syncthreads();
        float bval = 0.f;
        if (tid < DD) {
            float et = 0.f, vt = 0.f;
#pragma unroll
            for (int k = 0; k < NCH; ++k) { et += sEs[k][tid]; vt += sVs[k][tid]; }
            bval = et * vt;
            if (tid < NGRP) {
                float horizon = (times[b * LL + LL - 1] - times[b * LL + 1]) * 1e-4f;
                bval += horizon * spb[0][tid];
            }
        }
        if (warp < 2) {
            float s = warp_sum(bval);
            if (lane == 0) sbase[warp] = s;
        }
        __syncthreads();
        if (tid == 0) {
            long long ssum = (long long)(sfin - (u64_t)NGRP) >> 8;   // recover signed sum
            double logsum = (double)ssum * (1.0 / 1048576.0);
            out[b] = (float)((double)(sbase[0] + sbase[1]) + logsum);
            g_acc64[b] = 0ULL;   // reset for next launch (launches serialize)
        }
    }
}

extern "C" void kernel_launch(void* const* d_in, const int* in_sizes, int n_in,
                              void* d_out, int out_size) {
    const int*   ids   = (const int*)  d_in[0];
    const float* times = (const float*)d_in[1];
    // d_in[2] = mask (all ones, unused)
    const float* emb   = (const float*)d_in[3];
    const float* ut    = (const float*)d_in[4];
    const float* beta  = (const float*)d_in[5];
    float* out = (float*)d_out;

    hawkes_fused<<<BB * NGRP, 512>>>(ids, times, emb, ut, beta, out);
}

// round 13
// speedup vs baseline: 1.0469x; 1.0469x over previous
#include <cuda_runtime.h>
#include <math.h>

#define BB 4
#define LL 2048
#define DD 64
#define NGRP 16          // groups per batch
#define NCH 8            // 16-event chunks per group
#define CH16 16          // events per chunk
#define GEVT 128         // events per group

typedef unsigned long long u64_t;

// Scratch (no cudaMalloc allowed). Flags/counters are monotonic across launches (never reset).
__device__ float g_gcsum[BB][NGRP][DD];
__device__ float g_gesum[BB][NGRP][DD];
__device__ float g_gvsum[BB][NGRP][DD];
__device__ float g_gusum[BB][NGRP];
__device__ float g_accv[BB][NGRP];
__device__ int   g_flag[BB][NGRP];   // +1 per launch (launch-relative generations)
__device__ int   g_cnt[BB];          // +NGRP per launch

__device__ __forceinline__ float warp_sum(float v) {
#pragma unroll
    for (int o = 16; o > 0; o >>= 1) v += __shfl_xor_sync(0xffffffffu, v, o);
    return v;
}

// ---- packed f32x2 helpers (FFMA2 path, PTX-only) ----
__device__ __forceinline__ u64_t mul2(u64_t a, u64_t b) {
    u64_t d; asm("mul.rn.f32x2 %0, %1, %2;" : "=l"(d) : "l"(a), "l"(b)); return d;
}
__device__ __forceinline__ u64_t fma2(u64_t a, u64_t b, u64_t c) {
    u64_t d; asm("fma.rn.f32x2 %0, %1, %2, %3;" : "=l"(d) : "l"(a), "l"(b), "l"(c)); return d;
}
__device__ __forceinline__ u64_t add2(u64_t a, u64_t b) {
    u64_t d; asm("add.rn.f32x2 %0, %1, %2;" : "=l"(d) : "l"(a), "l"(b)); return d;
}
__device__ __forceinline__ u64_t pk2(float x, float y) {
    u64_t d; asm("mov.b64 %0, {%1, %2};" : "=l"(d) : "f"(x), "f"(y)); return d;
}
__device__ __forceinline__ float2 up2(u64_t v) {
    float2 r; asm("mov.b64 {%0, %1}, %2;" : "=f"(r.x), "=f"(r.y) : "l"(v)); return r;
}

__device__ __forceinline__ int ld_acq(const int* p) {
    int v;
    asm volatile("ld.acquire.gpu.u32 %0, [%1];" : "=r"(v) : "l"(p) : "memory");
    return v;
}
__device__ __forceinline__ void st_rel(int* p, int v) {
    asm volatile("st.release.gpu.u32 [%0], %1;" :: "l"(p), "r"(v) : "memory");
}

__global__ __launch_bounds__(512) void hawkes_fused(
    const int* __restrict__ ids, const float* __restrict__ times,
    const float* __restrict__ emb, const float* __restrict__ u_table,
    const float* __restrict__ beta, float* __restrict__ out)
{
    const int bg   = blockIdx.x;
    const int b    = bg >> 4;          // batch
    const int cg   = bg & 15;          // group
    const int tid  = threadIdx.x;
    const int lane = tid & 31;
    const int warp = tid >> 5;         // 0..15
    const int q    = tid >> 7;         // 32-event quartet, 0..3
    const int ht   = tid & 127;
    const int d    = ht & 63, g = ht >> 6;
    const int ch   = q * 2 + g;        // this thread's OWN 16-event chunk (gather)

    __shared__ __align__(16) float sE[GEVT][68];   // E rows, padded (272B row)
    __shared__ float sw[GEVT], sme[GEVT], svw[GEVT];
    __shared__ __align__(16) float sCs[NCH][DD];   // per-16-chunk csum
    __shared__ float sEs[NCH][DD], sVs[NCH][DD];
    __shared__ __align__(16) float spb[NCH][DD];   // per-16-chunk exclusive prefix
    __shared__ float sP[16][32];                   // phase-C d-slice partials
    __shared__ float spf[NGRP][DD];                // prefix rows (tail reuse)
    __shared__ float spfE[NGRP][DD], spfV[NGRP][DD];
    __shared__ float sures[4], slog[4], sbase[2];
    __shared__ int   slast;

    const float ab  = fabsf(beta[0]);
    const int   gen = g_flag[b][cg] + 1;   // own flag's pre-launch value (broadcast load)

    // ---- direct id loads (broadcast LDGs) — emb gather issues before any barrier ----
    const int cbase = b * LL + cg * GEVT + q * 32 + g * 16;
    int idv[16];
#pragma unroll
    for (int jj = 0; jj < 16; ++jj) idv[jj] = ids[cbase + jj];

    // ---- init warps (0,4,8,12 -> own 32-event quartet): per-event scalars; u in register ----
    float u_reg = 0.f;
    if ((warp & 3) == 0) {
        const int qe   = warp >> 2;
        const int gidx = b * LL + cg * GEVT + qe * 32 + lane;
        int id = ids[gidx];
        float tj    = times[gidx] * 1e-4f;
        float tlast = times[b * LL + LL - 1] * 1e-4f;
        float w = __expf(ab * tj);
        sw [qe * 32 + lane] = w;
        sme[qe * 32 + lane] = __expf(-ab * tj);
        svw[qe * 32 + lane] = 1.0f - __expf(-ab * tlast) * w;
        u_reg = u_table[id];
    }

    // ---- emb gather (dependent loads issue now, consumed after the barrier) ----
    float ev[16];
#pragma unroll
    for (int jj = 0; jj < 16; ++jj) ev[jj] = emb[(long)idv[jj] * DD + d];
    __syncthreads();   // sw/sme/svw ready

    // ---- consume: store sE rows + accumulate own 16-chunk sums ----
    float cs = 0.f, es = 0.f, vs = 0.f;
#pragma unroll
    for (int jj = 0; jj < 16; ++jj) {
        int j = ch * CH16 + jj;
        float e = ev[jj];
        sE[j][d] = e;
        cs = fmaf(e, sw[j], cs);
        es += e;
        vs = fmaf(e, svw[j], vs);
    }
    sCs[ch][d] = cs;     // thread's j-range IS chunk ch -> direct store, no combine stage
    sEs[ch][d] = es;
    sVs[ch][d] = vs;
    if ((warp & 3) == 0) {
        float uv = warp_sum(fabsf(u_reg));
        if (lane == 0) sures[warp >> 2] = uv;
    }
    __syncthreads();

    // ---- publish csum total (the ONLY cross-block dependency) + flag ----
    if (tid < DD) {
        float tot = 0.f;
#pragma unroll
        for (int k = 0; k < NCH; ++k) tot += sCs[k][tid];
        g_gcsum[b][cg][tid] = tot;
    }
    __syncthreads();
    if (tid == 0) st_rel(&g_flag[b][cg], gen);

    // ---- poll warp 15 starts now; tail-only sums publish; Gram hides the L2 latency ----
    if (warp == 15 && lane < cg) {
        const int* fp = &g_flag[b][lane];
        while (ld_acq(fp) < gen) { }
    }
    if (tid < DD) {
        float te = 0.f, tv = 0.f;
#pragma unroll
        for (int k = 0; k < NCH; ++k) { te += sEs[k][tid]; tv += sVs[k][tid]; }
        g_gesum[b][cg][tid] = te;
        g_gvsum[b][cg][tid] = tv;
        if (tid == 0)
            g_gusum[b][cg] = sures[0] + sures[1] + sures[2] + sures[3];
    }

    // ---- Gram (packed f32x2): warp = (pair p, D-slice qC); lanes 0-15 -> chunk 2p,
    //      lanes 16-31 -> chunk 2p+1. 16 j-iters.
    const int p  = warp >> 2, qC = warp & 3;
    const int hsel = lane & 16;            // 0 or 16: which chunk of the pair
    const int isub = lane & 15;            // event index within the 16-chunk
    const ulonglong2* arow =
        reinterpret_cast<const ulonglong2*>(&sE[p * 32 + lane][qC * 16]);
    ulonglong2 A0 = arow[0], A1 = arow[1], A2 = arow[2], A3 = arow[3];
    u64_t part2 = 0ULL;
#pragma unroll
    for (int j = 0; j < CH16; ++j) {
        const ulonglong2* ej =
            reinterpret_cast<const ulonglong2*>(&sE[p * 32 + hsel + j][qC * 16]);
        ulonglong2 B0 = ej[0], B1 = ej[1], B2 = ej[2], B3 = ej[3];
        u64_t s = mul2(A0.x, B0.x);
        s = fma2(A0.y, B0.y, s);
        s = fma2(A1.x, B1.x, s);
        s = fma2(A1.y, B1.y, s);
        s = fma2(A2.x, B2.x, s);
        s = fma2(A2.y, B2.y, s);
        s = fma2(A3.x, B3.x, s);
        s = fma2(A3.y, B3.y, s);
        float m = (j < isub) ? sw[p * 32 + hsel + j] : 0.f;   // strict lower triangle
        part2 = fma2(pk2(m, m), s, part2);
    }
    __syncthreads();   // polls complete (+ release visibility block-wide)

    // ---- exclusive group prefix: 256 threads, one float4 row-slice each ----
    const int i16 = tid >> 4;
    const int d4  = (tid & 15) * 4;
    if (tid < 256) {
        float4 v = make_float4(0.f, 0.f, 0.f, 0.f);
        if (i16 < cg) v = *reinterpret_cast<const float4*>(&g_gcsum[b][i16][d4]);
        *reinterpret_cast<float4*>(&spf[i16][d4]) = v;
    }
    __syncthreads();
    if (tid < DD) {
        float run = 0.f;
#pragma unroll
        for (int k = 0; k < NGRP; ++k) run += spf[k][tid];
        spb[0][tid] = run;
#pragma unroll
        for (int k = 0; k < NCH - 1; ++k) {
            run += sCs[k][tid];
            spb[k + 1][tid] = run;
        }
    }
    __syncthreads();

    // ---- add e_i·P term (per-half chunk prefix) and fold to scalar ----
    {
        const ulonglong2* pb = reinterpret_cast<const ulonglong2*>(
            &spb[p * 2 + (hsel >> 4)][qC * 16]);
        ulonglong2 P0 = pb[0], P1 = pb[1], P2 = pb[2], P3 = pb[3];
        u64_t s = mul2(A0.x, P0.x);
        s = fma2(A0.y, P0.y, s);
        s = fma2(A1.x, P1.x, s);
        s = fma2(A1.y, P1.y, s);
        s = fma2(A2.x, P2.x, s);
        s = fma2(A2.y, P2.y, s);
        s = fma2(A3.x, P3.x, s);
        s = fma2(A3.y, P3.y, s);
        part2 = add2(part2, s);
        float2 f = up2(part2);
        sP[warp][lane] = f.x + f.y;
    }
    __syncthreads();
    if ((warp & 3) == 0) {
        const int pp = warp >> 2;      // pair pp: lanes span its 32 events
        float dp  = sP[pp * 4][lane] + sP[pp * 4 + 1][lane]
                  + sP[pp * 4 + 2][lane] + sP[pp * 4 + 3][lane];
        float s1  = ab * sme[pp * 32 + lane] * dp;
        float lam = fabsf(s1 + fabsf(u_reg)) + 1e-6f;
        float v   = warp_sum(-__logf(lam));
        if (lane == 0) slog[pp] = v;
    }
    __syncthreads();

    // ---- completion ticket; LAST group per batch computes base term + reduces ----
    if (tid == 0) {
        g_accv[b][cg] = slog[0] + slog[1] + slog[2] + slog[3];
        __threadfence();
        int t = atomicAdd(&g_cnt[b], 1);
        slast = ((t & (NGRP - 1)) == (NGRP - 1)) ? 1 : 0;
    }
    __syncthreads();
    if (slast) {
        __threadfence();
        if (tid < 256) {   // Et/Vt rows (published long before tickets)
            float4 ve = *reinterpret_cast<const float4*>(&g_gesum[b][i16][d4]);
            float4 vv = *reinterpret_cast<const float4*>(&g_gvsum[b][i16][d4]);
            *reinterpret_cast<float4*>(&spfE[i16][d4]) = ve;
            *reinterpret_cast<float4*>(&spfV[i16][d4]) = vv;
        }
        if (tid < NGRP) spf[0][tid] = __ldcg(&g_accv[b][tid]);
        __syncthreads();
        float bval = 0.f;
        if (tid < DD) {
            float et = 0.f, vt = 0.f;
#pragma unroll
            for (int k = 0; k < NGRP; ++k) { et += spfE[k][tid]; vt += spfV[k][tid]; }
            bval = et * vt;
            if (tid < NGRP) {
                float horizon = (times[b * LL + LL - 1] - times[b * LL + 1]) * 1e-4f;
                bval += horizon * __ldcg(&g_gusum[b][tid]);
            }
        }
        if (warp < 2) {
            float s = warp_sum(bval);
            if (lane == 0) sbase[warp] = s;
        }
        __syncthreads();
        if (tid == 0) {
            float s = 0.f;
            for (int k = 0; k < NGRP; ++k) s += spf[0][k];   // fixed order -> deterministic
            out[b] = s + sbase[0] + sbase[1];
        }
    }
}

extern "C" void kernel_launch(void* const* d_in, const int* in_sizes, int n_in,
                              void* d_out, int out_size) {
    const int*   ids   = (const int*)  d_in[0];
    const float* times = (const float*)d_in[1];
    // d_in[2] = mask (all ones, unused)
    const float* emb   = (const float*)d_in[3];
    const float* ut    = (const float*)d_in[4];
    const float* beta  = (const float*)d_in[5];
    float* out = (float*)d_out;

    hawkes_fused<<<BB * NGRP, 512>>>(ids, times, emb, ut, beta, out);
}

// round 14
// speedup vs baseline: 1.3137x; 1.2549x over previous
#include <cuda_runtime.h>
#include <math.h>

#define BB 4
#define LL 2048
#define DD 64
#define NGRP 16          // groups per batch
#define NCH 16           // 8-event chunks per group
#define GEVT 128         // events per group

typedef unsigned long long u64_t;

// Scratch (no cudaMalloc allowed). Flags/counters are monotonic across launches (never reset).
__device__ float g_gcsum[BB][NGRP][DD];
__device__ float g_gesum[BB][NGRP][DD];
__device__ float g_gvsum[BB][NGRP][DD];
__device__ float g_gusum[BB][NGRP];
__device__ float g_accv[BB][NGRP];
__device__ int   g_flag[BB][NGRP];   // +1 per launch (launch-relative generations)
__device__ int   g_cnt[BB];          // +NGRP per launch

__device__ __forceinline__ float warp_sum(float v) {
#pragma unroll
    for (int o = 16; o > 0; o >>= 1) v += __shfl_xor_sync(0xffffffffu, v, o);
    return v;
}

// ---- packed f32x2 helpers (FFMA2 path, PTX-only) ----
__device__ __forceinline__ u64_t mul2(u64_t a, u64_t b) {
    u64_t d; asm("mul.rn.f32x2 %0, %1, %2;" : "=l"(d) : "l"(a), "l"(b)); return d;
}
__device__ __forceinline__ u64_t fma2(u64_t a, u64_t b, u64_t c) {
    u64_t d; asm("fma.rn.f32x2 %0, %1, %2, %3;" : "=l"(d) : "l"(a), "l"(b), "l"(c)); return d;
}
__device__ __forceinline__ u64_t add2(u64_t a, u64_t b) {
    u64_t d; asm("add.rn.f32x2 %0, %1, %2;" : "=l"(d) : "l"(a), "l"(b)); return d;
}
__device__ __forceinline__ u64_t pk2(float x, float y) {
    u64_t d; asm("mov.b64 %0, {%1, %2};" : "=l"(d) : "f"(x), "f"(y)); return d;
}
__device__ __forceinline__ float2 up2(u64_t v) {
    float2 r; asm("mov.b64 {%0, %1}, %2;" : "=f"(r.x), "=f"(r.y) : "l"(v)); return r;
}

__device__ __forceinline__ int ld_acq(const int* p) {
    int v;
    asm volatile("ld.acquire.gpu.u32 %0, [%1];" : "=r"(v) : "l"(p) : "memory");
    return v;
}
__device__ __forceinline__ void st_rel(int* p, int v) {
    asm volatile("st.release.gpu.u32 [%0], %1;" :: "l"(p), "r"(v) : "memory");
}

__global__ __launch_bounds__(512) void hawkes_fused(
    const int* __restrict__ ids, const float* __restrict__ times,
    const float* __restrict__ emb, const float* __restrict__ u_table,
    const float* __restrict__ beta, float* __restrict__ out)
{
    const int bg   = blockIdx.x;
    const int b    = bg >> 4;          // batch
    const int cg   = bg & 15;          // group
    const int tid  = threadIdx.x;
    const int lane = tid & 31;
    const int warp = tid >> 5;         // 0..15
    const int r    = tid >> 6;         // gather row-slice, 0..7 (16 events each)
    const int d    = tid & 63;

    __shared__ __align__(16) float sE[GEVT][68];   // E rows, padded (272B row)
    __shared__ float sw[GEVT], sme[GEVT], svw[GEVT];
    __shared__ __align__(16) float sCs[NCH][DD];   // per-8-chunk csum
    __shared__ float sEs[NCH][DD], sVs[NCH][DD];
    __shared__ __align__(16) float spb[NCH][DD];   // per-8-chunk exclusive prefix
    __shared__ float sP[16][32];                   // phase-C d-slice partials
    __shared__ float spf[NGRP][DD];                // prefix rows (tail reuse)
    __shared__ float spfE[NGRP][DD], spfV[NGRP][DD];
    __shared__ float sures[4], slog[4], sbase[2];
    __shared__ int   slast;

    const float ab  = fabsf(beta[0]);
    const int   gen = g_flag[b][cg] + 1;   // own flag's pre-launch value (broadcast load)

    // ---- direct id loads (broadcast LDGs) — emb gather issues before any barrier ----
    const int cbase = b * LL + cg * GEVT + r * 16;
    int idv[16];
#pragma unroll
    for (int jj = 0; jj < 16; ++jj) idv[jj] = ids[cbase + jj];

    // ---- init warps (0,4,8,12 -> own 32-event quartet): per-event scalars; u in register ----
    float u_reg = 0.f;
    if ((warp & 3) == 0) {
        const int qe   = warp >> 2;
        const int gidx = b * LL + cg * GEVT + qe * 32 + lane;
        int id = ids[gidx];
        float tj    = times[gidx] * 1e-4f;
        float tlast = times[b * LL + LL - 1] * 1e-4f;
        float w = __expf(ab * tj);
        sw [qe * 32 + lane] = w;
        sme[qe * 32 + lane] = __expf(-ab * tj);
        svw[qe * 32 + lane] = 1.0f - __expf(-ab * tlast) * w;
        u_reg = u_table[id];
    }

    // ---- emb gather (independent LDGs in flight across the barrier) ----
    float ev[16];
#pragma unroll
    for (int jj = 0; jj < 16; ++jj) ev[jj] = emb[(long)idv[jj] * DD + d];
    __syncthreads();   // B1: sw/sme/svw ready

    // ---- consume: store sE rows + per-8-chunk sums (chunks 2r and 2r+1) ----
    float cs0 = 0.f, es0 = 0.f, vs0 = 0.f, cs1 = 0.f, es1 = 0.f, vs1 = 0.f;
#pragma unroll
    for (int jj = 0; jj < 8; ++jj) {
        int j = r * 16 + jj;
        float e = ev[jj];
        sE[j][d] = e;
        cs0 = fmaf(e, sw[j], cs0); es0 += e; vs0 = fmaf(e, svw[j], vs0);
    }
#pragma unroll
    for (int jj = 8; jj < 16; ++jj) {
        int j = r * 16 + jj;
        float e = ev[jj];
        sE[j][d] = e;
        cs1 = fmaf(e, sw[j], cs1); es1 += e; vs1 = fmaf(e, svw[j], vs1);
    }
    sCs[2 * r][d] = cs0;  sCs[2 * r + 1][d] = cs1;
    sEs[2 * r][d] = es0;  sEs[2 * r + 1][d] = es1;
    sVs[2 * r][d] = vs0;  sVs[2 * r + 1][d] = vs1;
    if ((warp & 3) == 0) {
        float uv = warp_sum(fabsf(u_reg));
        if (lane == 0) sures[warp >> 2] = uv;
    }
    __syncthreads();   // B2: sE/sCs/sEs/sVs ready

    // ---- publish csum total (the ONLY cross-block dependency) + flag ----
    if (tid < DD) {
        float tot = 0.f;
#pragma unroll
        for (int k = 0; k < NCH; ++k) tot += sCs[k][tid];
        g_gcsum[b][cg][tid] = tot;
    }
    __syncthreads();
    if (tid == 0) st_rel(&g_flag[b][cg], gen);

    // ---- poll warp 15 starts now; tail-only sums publish; Gram hides the L2 latency ----
    if (warp == 15 && lane < cg) {
        const int* fp = &g_flag[b][lane];
        while (ld_acq(fp) < gen) { }
    }
    if (tid < DD) {
        float te = 0.f, tv = 0.f;
#pragma unroll
        for (int k = 0; k < NCH; ++k) { te += sEs[k][tid]; tv += sVs[k][tid]; }
        g_gesum[b][cg][tid] = te;
        g_gvsum[b][cg][tid] = tv;
        if (tid == 0)
            g_gusum[b][cg] = sures[0] + sures[1] + sures[2] + sures[3];
    }

    // ---- Gram (packed f32x2): warp = (quartet p, D-slice qC); 4×8-lane subgroups,
    //      lanes (hsel..hsel+7) <-> chunk p*4 + hsel/8. 8 j-iters.
    const int p = warp >> 2, qC = warp & 3;
    const int hsel = lane & 24;            // 0,8,16,24: chunk-of-8 within the quartet
    const int isub = lane & 7;             // event index within the 8-chunk
    const ulonglong2* arow =
        reinterpret_cast<const ulonglong2*>(&sE[p * 32 + lane][qC * 16]);
    ulonglong2 A0 = arow[0], A1 = arow[1], A2 = arow[2], A3 = arow[3];
    u64_t part2 = 0ULL;
#pragma unroll
    for (int j = 0; j < 8; ++j) {
        const ulonglong2* ej =
            reinterpret_cast<const ulonglong2*>(&sE[p * 32 + hsel + j][qC * 16]);
        ulonglong2 B0 = ej[0], B1 = ej[1], B2 = ej[2], B3 = ej[3];
        u64_t s = mul2(A0.x, B0.x);
        s = fma2(A0.y, B0.y, s);
        s = fma2(A1.x, B1.x, s);
        s = fma2(A1.y, B1.y, s);
        s = fma2(A2.x, B2.x, s);
        s = fma2(A2.y, B2.y, s);
        s = fma2(A3.x, B3.x, s);
        s = fma2(A3.y, B3.y, s);
        float m = (j < isub) ? sw[p * 32 + hsel + j] : 0.f;   // strict lower triangle
        part2 = fma2(pk2(m, m), s, part2);
    }
    __syncthreads();   // B3: polls + publishes complete (release visibility block-wide)

    // ---- exclusive group prefix: 256 threads, one float4 row-slice each ----
    const int i16 = tid >> 4;
    const int d4  = (tid & 15) * 4;
    if (tid < 256) {
        float4 v = make_float4(0.f, 0.f, 0.f, 0.f);
        if (i16 < cg) v = *reinterpret_cast<const float4*>(&g_gcsum[b][i16][d4]);
        *reinterpret_cast<float4*>(&spf[i16][d4]) = v;
    }
    __syncthreads();
    if (tid < DD) {
        float run = 0.f;
#pragma unroll
        for (int k = 0; k < NGRP; ++k) run += spf[k][tid];
        spb[0][tid] = run;
#pragma unroll
        for (int k = 0; k < NCH - 1; ++k) {
            run += sCs[k][tid];
            spb[k + 1][tid] = run;
        }
    }
    __syncthreads();   // B4: spb ready

    // ---- add e_i·P term (per-8-chunk prefix) and fold to scalar ----
    {
        const int cidx = p * 4 + (lane >> 3);
        const ulonglong2* pb = reinterpret_cast<const ulonglong2*>(&spb[cidx][qC * 16]);
        ulonglong2 P0 = pb[0], P1 = pb[1], P2 = pb[2], P3 = pb[3];
        u64_t s = mul2(A0.x, P0.x);
        s = fma2(A0.y, P0.y, s);
        s = fma2(A1.x, P1.x, s);
        s = fma2(A1.y, P1.y, s);
        s = fma2(A2.x, P2.x, s);
        s = fma2(A2.y, P2.y, s);
        s = fma2(A3.x, P3.x, s);
        s = fma2(A3.y, P3.y, s);
        part2 = add2(part2, s);
        float2 f = up2(part2);
        sP[warp][lane] = f.x + f.y;
    }
    __syncthreads();   // B5
    if ((warp & 3) == 0) {
        const int pp = warp >> 2;      // quartet pp: lanes span its 32 events
        float dp  = sP[pp * 4][lane] + sP[pp * 4 + 1][lane]
                  + sP[pp * 4 + 2][lane] + sP[pp * 4 + 3][lane];
        float s1  = ab * sme[pp * 32 + lane] * dp;
        float lam = fabsf(s1 + fabsf(u_reg)) + 1e-6f;
        float v   = warp_sum(-__logf(lam));
        if (lane == 0) slog[pp] = v;
    }
    __syncthreads();   // B6

    // ---- completion ticket; LAST group per batch computes base term + reduces ----
    if (tid == 0) {
        g_accv[b][cg] = slog[0] + slog[1] + slog[2] + slog[3];
        __threadfence();
        int t = atomicAdd(&g_cnt[b], 1);
        slast = ((t & (NGRP - 1)) == (NGRP - 1)) ? 1 : 0;
    }
    __syncthreads();   // B7
    if (slast) {
        __threadfence();
        if (tid < 256) {   // Et/Vt rows (published long before tickets)
            float4 ve = *reinterpret_cast<const float4*>(&g_gesum[b][i16][d4]);
            float4 vv = *reinterpret_cast<const float4*>(&g_gvsum[b][i16][d4]);
            *reinterpret_cast<float4*>(&spfE[i16][d4]) = ve;
            *reinterpret_cast<float4*>(&spfV[i16][d4]) = vv;
        }
        if (tid < NGRP) spf[0][tid] = __ldcg(&g_accv[b][tid]);
        __syncthreads();
        float bval = 0.f;
        if (tid < DD) {
            float et = 0.f, vt = 0.f;
#pragma unroll
            for (int k = 0; k < NGRP; ++k) { et += spfE[k][tid]; vt += spfV[k][tid]; }
            bval = et * vt;
            if (tid < NGRP) {
                float horizon = (times[b * LL + LL - 1] - times[b * LL + 1]) * 1e-4f;
                bval += horizon * __ldcg(&g_gusum[b][tid]);
            }
        }
        if (warp < 2) {
            float s = warp_sum(bval);
            if (lane == 0) sbase[warp] = s;
        }
        __syncthreads();
        if (tid == 0) {
            float s = 0.f;
            for (int k = 0; k < NGRP; ++k) s += spf[0][k];   // fixed order -> deterministic
            out[b] = s + sbase[0] + sbase[1];
        }
    }
}

extern "C" void kernel_launch(void* const* d_in, const int* in_sizes, int n_in,
                              void* d_out, int out_size) {
    const int*   ids   = (const int*)  d_in[0];
    const float* times = (const float*)d_in[1];
    // d_in[2] = mask (all ones, unused)
    const float* emb   = (const float*)d_in[3];
    const float* ut    = (const float*)d_in[4];
    const float* beta  = (const float*)d_in[5];
    float* out = (float*)d_out;

    hawkes_fused<<<BB * NGRP, 512>>>(ids, times, emb, ut, beta, out);
}

// round 15
// speedup vs baseline: 1.3202x; 1.0049x over previous
#include <cuda_runtime.h>
#include <math.h>

#define BB 4
#define LL 2048
#define DD 64
#define NGRP 16          // groups per batch
#define NCH 16           // 8-event chunks per group
#define GEVT 128         // events per group

typedef unsigned long long u64_t;

// Scratch (no cudaMalloc allowed). Flags/counters are monotonic across launches (never reset).
__device__ float g_gcsum[BB][NGRP][DD];
__device__ float g_gesum[BB][NGRP][DD];
__device__ float g_gvsum[BB][NGRP][DD];
__device__ float g_gusum[BB][NGRP];
__device__ float g_accv[BB][NGRP];
__device__ int   g_flag[BB][NGRP];   // +1 per launch (launch-relative generations)
__device__ int   g_cnt[BB];          // +NGRP per launch

__device__ __forceinline__ float warp_sum(float v) {
#pragma unroll
    for (int o = 16; o > 0; o >>= 1) v += __shfl_xor_sync(0xffffffffu, v, o);
    return v;
}

// ---- packed f32x2 helpers (FFMA2 path, PTX-only) ----
__device__ __forceinline__ u64_t mul2(u64_t a, u64_t b) {
    u64_t d; asm("mul.rn.f32x2 %0, %1, %2;" : "=l"(d) : "l"(a), "l"(b)); return d;
}
__device__ __forceinline__ u64_t fma2(u64_t a, u64_t b, u64_t c) {
    u64_t d; asm("fma.rn.f32x2 %0, %1, %2, %3;" : "=l"(d) : "l"(a), "l"(b), "l"(c)); return d;
}
__device__ __forceinline__ u64_t add2(u64_t a, u64_t b) {
    u64_t d; asm("add.rn.f32x2 %0, %1, %2;" : "=l"(d) : "l"(a), "l"(b)); return d;
}
__device__ __forceinline__ u64_t pk2(float x, float y) {
    u64_t d; asm("mov.b64 %0, {%1, %2};" : "=l"(d) : "f"(x), "f"(y)); return d;
}
__device__ __forceinline__ float2 up2(u64_t v) {
    float2 r; asm("mov.b64 {%0, %1}, %2;" : "=f"(r.x), "=f"(r.y) : "l"(v)); return r;
}

__device__ __forceinline__ int ld_acq(const int* p) {
    int v;
    asm volatile("ld.acquire.gpu.u32 %0, [%1];" : "=r"(v) : "l"(p) : "memory");
    return v;
}
__device__ __forceinline__ void st_rel(int* p, int v) {
    asm volatile("st.release.gpu.u32 [%0], %1;" :: "l"(p), "r"(v) : "memory");
}

__global__ __launch_bounds__(512) void hawkes_fused(
    const int* __restrict__ ids, const float* __restrict__ times,
    const float* __restrict__ emb, const float* __restrict__ u_table,
    const float* __restrict__ beta, float* __restrict__ out)
{
    const int bg   = blockIdx.x;
    const int b    = bg >> 4;          // batch
    const int cg   = bg & 15;          // group
    const int tid  = threadIdx.x;
    const int lane = tid & 31;
    const int warp = tid >> 5;         // 0..15
    const int r    = tid >> 6;         // gather row-slice, 0..7 (16 events each)
    const int d    = tid & 63;

    __shared__ __align__(16) float sE[GEVT][68];   // E rows, padded (272B row)
    __shared__ float sw[GEVT], sme[GEVT], svw[GEVT];
    __shared__ __align__(16) float sCs[NCH][DD];   // per-8-chunk csum
    __shared__ float sEs[NCH][DD], sVs[NCH][DD];
    __shared__ __align__(16) float spb[NCH][DD];   // per-8-chunk exclusive prefix
    __shared__ float sP[16][32];                   // phase-C d-slice partials
    __shared__ float spf[NGRP][DD];                // prefix rows (warp-15 prefetched; tail reuse)
    __shared__ float spfE[NGRP][DD], spfV[NGRP][DD];
    __shared__ float sures[4], slog[4], sbase[2];
    __shared__ int   slast;

    const float ab  = fabsf(beta[0]);
    const int   gen = g_flag[b][cg] + 1;   // own flag's pre-launch value (broadcast load)

    // ---- direct id loads (broadcast LDGs) — emb gather issues before any barrier ----
    const int cbase = b * LL + cg * GEVT + r * 16;
    int idv[16];
#pragma unroll
    for (int jj = 0; jj < 16; ++jj) idv[jj] = ids[cbase + jj];

    // ---- init warps (0,4,8,12 -> own 32-event quartet): per-event scalars; u in register ----
    float u_reg = 0.f;
    if ((warp & 3) == 0) {
        const int qe   = warp >> 2;
        const int gidx = b * LL + cg * GEVT + qe * 32 + lane;
        int id = ids[gidx];
        float tj    = times[gidx] * 1e-4f;
        float tlast = times[b * LL + LL - 1] * 1e-4f;
        float w = __expf(ab * tj);
        sw [qe * 32 + lane] = w;
        sme[qe * 32 + lane] = __expf(-ab * tj);
        svw[qe * 32 + lane] = 1.0f - __expf(-ab * tlast) * w;
        u_reg = u_table[id];
    }

    // ---- emb gather (independent LDGs in flight across the barrier) ----
    float ev[16];
#pragma unroll
    for (int jj = 0; jj < 16; ++jj) ev[jj] = emb[(long)idv[jj] * DD + d];
    __syncthreads();   // B1: sw/sme/svw ready

    // ---- consume: store sE rows + per-8-chunk sums (chunks 2r and 2r+1) ----
    float cs0 = 0.f, es0 = 0.f, vs0 = 0.f, cs1 = 0.f, es1 = 0.f, vs1 = 0.f;
#pragma unroll
    for (int jj = 0; jj < 8; ++jj) {
        int j = r * 16 + jj;
        float e = ev[jj];
        sE[j][d] = e;
        cs0 = fmaf(e, sw[j], cs0); es0 += e; vs0 = fmaf(e, svw[j], vs0);
    }
#pragma unroll
    for (int jj = 8; jj < 16; ++jj) {
        int j = r * 16 + jj;
        float e = ev[jj];
        sE[j][d] = e;
        cs1 = fmaf(e, sw[j], cs1); es1 += e; vs1 = fmaf(e, svw[j], vs1);
    }
    sCs[2 * r][d] = cs0;  sCs[2 * r + 1][d] = cs1;
    sEs[2 * r][d] = es0;  sEs[2 * r + 1][d] = es1;
    sVs[2 * r][d] = vs0;  sVs[2 * r + 1][d] = vs1;
    if ((warp & 3) == 0) {
        float uv = warp_sum(fabsf(u_reg));
        if (lane == 0) sures[warp >> 2] = uv;
    }
    __syncthreads();   // B2: sE/sCs/sEs/sVs ready

    // ---- publish csum total (the ONLY cross-block dependency) + flag ----
    if (tid < DD) {
        float tot = 0.f;
#pragma unroll
        for (int k = 0; k < NCH; ++k) tot += sCs[k][tid];
        g_gcsum[b][cg][tid] = tot;
    }
    __syncthreads();
    if (tid == 0) st_rel(&g_flag[b][cg], gen);

    // ---- warp 15: poll earlier groups, then ISSUE prefix-row loads (consumed after
    //      its Gram — L2 latency hides under the FFMA2 loop). Others publish tail sums.
    float2 pf[NGRP - 1];
    if (warp == 15) {
        if (lane < cg) {
            const int* fp = &g_flag[b][lane];
            while (ld_acq(fp) < gen) { }
        }
        __syncwarp();
#pragma unroll
        for (int cp = 0; cp < NGRP - 1; ++cp) {
            if (cp < cg)
                pf[cp] = *reinterpret_cast<const float2*>(&g_gcsum[b][cp][lane * 2]);
        }
    }
    if (tid < DD) {
        float te = 0.f, tv = 0.f;
#pragma unroll
        for (int k = 0; k < NCH; ++k) { te += sEs[k][tid]; tv += sVs[k][tid]; }
        g_gesum[b][cg][tid] = te;
        g_gvsum[b][cg][tid] = tv;
        if (tid == 0)
            g_gusum[b][cg] = sures[0] + sures[1] + sures[2] + sures[3];
    }

    // ---- Gram (packed f32x2): warp = (quartet p, D-slice qC); 4×8-lane subgroups,
    //      lanes (hsel..hsel+7) <-> chunk p*4 + hsel/8. 8 j-iters.
    const int p = warp >> 2, qC = warp & 3;
    const int hsel = lane & 24;            // 0,8,16,24: chunk-of-8 within the quartet
    const int isub = lane & 7;             // event index within the 8-chunk
    const ulonglong2* arow =
        reinterpret_cast<const ulonglong2*>(&sE[p * 32 + lane][qC * 16]);
    ulonglong2 A0 = arow[0], A1 = arow[1], A2 = arow[2], A3 = arow[3];
    u64_t part2 = 0ULL;
#pragma unroll
    for (int j = 0; j < 8; ++j) {
        const ulonglong2* ej =
            reinterpret_cast<const ulonglong2*>(&sE[p * 32 + hsel + j][qC * 16]);
        ulonglong2 B0 = ej[0], B1 = ej[1], B2 = ej[2], B3 = ej[3];
        u64_t s = mul2(A0.x, B0.x);
        s = fma2(A0.y, B0.y, s);
        s = fma2(A1.x, B1.x, s);
        s = fma2(A1.y, B1.y, s);
        s = fma2(A2.x, B2.x, s);
        s = fma2(A2.y, B2.y, s);
        s = fma2(A3.x, B3.x, s);
        s = fma2(A3.y, B3.y, s);
        float m = (j < isub) ? sw[p * 32 + hsel + j] : 0.f;   // strict lower triangle
        part2 = fma2(pk2(m, m), s, part2);
    }
    // ---- warp 15: consume the prefetched prefix rows into smem ----
    if (warp == 15) {
#pragma unroll
        for (int cp = 0; cp < NGRP - 1; ++cp) {
            if (cp < cg)
                *reinterpret_cast<float2*>(&spf[cp][lane * 2]) = pf[cp];
        }
    }
    __syncthreads();   // B3: Gram + polls + prefix rows in smem (release visibility)

    // ---- spb: exclusive prefix over groups (<cg rows) then chunks, 64 threads ----
    if (tid < DD) {
        float run = 0.f;
        for (int cp = 0; cp < cg; ++cp) run += spf[cp][tid];
        spb[0][tid] = run;
#pragma unroll
        for (int k = 0; k < NCH - 1; ++k) {
            run += sCs[k][tid];
            spb[k + 1][tid] = run;
        }
    }
    __syncthreads();   // B4: spb ready

    // ---- add e_i·P term (per-8-chunk prefix) and fold to scalar ----
    {
        const int cidx = p * 4 + (lane >> 3);
        const ulonglong2* pb = reinterpret_cast<const ulonglong2*>(&spb[cidx][qC * 16]);
        ulonglong2 P0 = pb[0], P1 = pb[1], P2 = pb[2], P3 = pb[3];
        u64_t s = mul2(A0.x, P0.x);
        s = fma2(A0.y, P0.y, s);
        s = fma2(A1.x, P1.x, s);
        s = fma2(A1.y, P1.y, s);
        s = fma2(A2.x, P2.x, s);
        s = fma2(A2.y, P2.y, s);
        s = fma2(A3.x, P3.x, s);
        s = fma2(A3.y, P3.y, s);
        part2 = add2(part2, s);
        float2 f = up2(part2);
        sP[warp][lane] = f.x + f.y;
    }
    __syncthreads();   // B5
    if ((warp & 3) == 0) {
        const int pp = warp >> 2;      // quartet pp: lanes span its 32 events
        float dp  = sP[pp * 4][lane] + sP[pp * 4 + 1][lane]
                  + sP[pp * 4 + 2][lane] + sP[pp * 4 + 3][lane];
        float s1  = ab * sme[pp * 32 + lane] * dp;
        float lam = fabsf(s1 + fabsf(u_reg)) + 1e-6f;
        float v   = warp_sum(-__logf(lam));
        if (lane == 0) slog[pp] = v;
    }
    __syncthreads();   // B6

    // ---- completion ticket; LAST group per batch computes base term + reduces ----
    if (tid == 0) {
        g_accv[b][cg] = slog[0] + slog[1] + slog[2] + slog[3];
        __threadfence();
        int t = atomicAdd(&g_cnt[b], 1);
        slast = ((t & (NGRP - 1)) == (NGRP - 1)) ? 1 : 0;
    }
    __syncthreads();   // B7
    if (slast) {
        __threadfence();
        const int i16 = tid >> 4;
        const int d4  = (tid & 15) * 4;
        if (tid < 256) {   // Et/Vt rows (published long before tickets)
            float4 ve = *reinterpret_cast<const float4*>(&g_gesum[b][i16][d4]);
            float4 vv = *reinterpret_cast<const float4*>(&g_gvsum[b][i16][d4]);
            *reinterpret_cast<float4*>(&spfE[i16][d4]) = ve;
            *reinterpret_cast<float4*>(&spfV[i16][d4]) = vv;
        }
        if (tid < NGRP) spf[0][tid] = __ldcg(&g_accv[b][tid]);
        __syncthreads();
        float bval = 0.f;
        if (tid < DD) {
            float et = 0.f, vt = 0.f;
#pragma unroll
            for (int k = 0; k < NGRP; ++k) { et += spfE[k][tid]; vt += spfV[k][tid]; }
            bval = et * vt;
            if (tid < NGRP) {
                float horizon = (times[b * LL + LL - 1] - times[b * LL + 1]) * 1e-4f;
                bval += horizon * __ldcg(&g_gusum[b][tid]);
            }
        }
        if (warp < 2) {
            float s = warp_sum(bval);
            if (lane == 0) sbase[warp] = s;
        }
        __syncthreads();
        if (tid == 0) {
            float s = 0.f;
            for (int k = 0; k < NGRP; ++k) s += spf[0][k];   // fixed order -> deterministic
            out[b] = s + sbase[0] + sbase[1];
        }
    }
}

extern "C" void kernel_launch(void* const* d_in, const int* in_sizes, int n_in,
                              void* d_out, int out_size) {
    const int*   ids   = (const int*)  d_in[0];
    const float* times = (const float*)d_in[1];
    // d_in[2] = mask (all ones, unused)
    const float* emb   = (const float*)d_in[3];
    const float* ut    = (const float*)d_in[4];
    const float* beta  = (const float*)d_in[5];
    float* out = (float*)d_out;

    hawkes_fused<<<BB * NGRP, 512>>>(ids, times, emb, ut, beta, out);
}